// round 1
// baseline (speedup 1.0000x reference)
#include <cuda_runtime.h>
#include <math.h>
#include <stdint.h>

#define NTOK 4096
#define HD   1024
#define FF   4096
#define NE   8
#define BM   64
#define BN   64
#define BK   16
#define MAXR 8704                 // 8192 routed rows + worst-case per-expert padding
#define MAXTILES (MAXR / BM)      // 136

// ---------------- scratch (device globals; no runtime allocation) ----------------
__device__ float g_h1[(size_t)MAXR * FF];   // gelu(X@W1)  ~142 MB
__device__ float g_o [(size_t)MAXR * HD];   // H1@W2       ~36 MB
__device__ int   g_tope[NTOK * 2];
__device__ float g_topw[NTOK * 2];
__device__ int   g_rows[MAXR];              // grouped row -> token (-1 = pad)
__device__ int   g_t2r [NTOK * 2];          // (token,k) -> grouped row
__device__ int   g_counts[NE];
__device__ int   g_cursor[NE];
__device__ int   g_poff[NE + 1];            // padded group offsets

__device__ __forceinline__ float gelu_f(float v) {
    const float c = 0.7978845608028654f;    // sqrt(2/pi)
    float u = c * (v + 0.044715f * v * v * v);
    return 0.5f * v * (1.f + tanhf(u));
}

// ---------------- 1. init ----------------
__global__ void init_kernel() {
    int i = blockIdx.x * blockDim.x + threadIdx.x;
    if (i < MAXR) g_rows[i] = -1;
    if (i < NE) { g_counts[i] = 0; g_cursor[i] = 0; }
}

// ---------------- 2. router ----------------
__global__ __launch_bounds__(128) void router_kernel(const float* __restrict__ x,
                                                     const float* __restrict__ Wg,
                                                     float* __restrict__ logits) {
    int t = blockIdx.x;
    const float* xr = x + (size_t)t * HD;
    float acc[NE];
#pragma unroll
    for (int e = 0; e < NE; e++) acc[e] = 0.f;
    for (int j = threadIdx.x; j < HD; j += 128) {
        float xv = xr[j];
        const float4* w4 = reinterpret_cast<const float4*>(Wg + (size_t)j * NE);
        float4 wa = w4[0], wb = w4[1];
        acc[0] += xv * wa.x; acc[1] += xv * wa.y; acc[2] += xv * wa.z; acc[3] += xv * wa.w;
        acc[4] += xv * wb.x; acc[5] += xv * wb.y; acc[6] += xv * wb.z; acc[7] += xv * wb.w;
    }
    __shared__ float s[4][NE];
    int lane = threadIdx.x & 31, warp = threadIdx.x >> 5;
#pragma unroll
    for (int e = 0; e < NE; e++) {
        float v = acc[e];
#pragma unroll
        for (int o = 16; o; o >>= 1) v += __shfl_down_sync(0xffffffffu, v, o);
        if (lane == 0) s[warp][e] = v;
    }
    __syncthreads();
    if (threadIdx.x == 0) {
        float l[NE];
#pragma unroll
        for (int e = 0; e < NE; e++) {
            l[e] = s[0][e] + s[1][e] + s[2][e] + s[3][e];
            logits[(size_t)t * NE + e] = l[e];
        }
        int e0 = 0;
#pragma unroll
        for (int e = 1; e < NE; e++) if (l[e] > l[e0]) e0 = e;
        int e1 = (e0 == 0) ? 1 : 0;
#pragma unroll
        for (int e = 0; e < NE; e++) if (e != e0 && l[e] > l[e1]) e1 = e;
        float w0 = 1.f / (1.f + expf(l[e1] - l[e0]));   // softmax of top-2
        float w1 = 1.f - w0;
        g_tope[t * 2]     = e0; g_tope[t * 2 + 1] = e1;
        g_topw[t * 2]     = w0; g_topw[t * 2 + 1] = w1;
        atomicAdd(&g_counts[e0], 1);
        atomicAdd(&g_counts[e1], 1);
    }
}

// ---------------- 3. offsets ----------------
__global__ void offsets_kernel() {
    int off = 0;
#pragma unroll
    for (int e = 0; e < NE; e++) {
        g_poff[e] = off;
        off += (g_counts[e] + BM - 1) / BM * BM;
    }
    g_poff[NE] = off;
}

// ---------------- 4. scatter ----------------
__global__ void scatter_kernel() {
    int t = blockIdx.x * blockDim.x + threadIdx.x;
    if (t >= NTOK) return;
#pragma unroll
    for (int k = 0; k < 2; k++) {
        int e = g_tope[t * 2 + k];
        int slot = atomicAdd(&g_cursor[e], 1);
        int r = g_poff[e] + slot;
        g_rows[r] = t;
        g_t2r[t * 2 + k] = r;
    }
}

// ---------------- 5. GEMM1: H1 = gelu(gather(X) @ W1[e]) ----------------
__global__ __launch_bounds__(256) void gemm1_kernel(const float* __restrict__ x,
                                                    const float* __restrict__ W1) {
    __shared__ float As[BK][BM + 4];
    __shared__ float Bs[BK][BN];
    __shared__ int   stok[BM];
    int r0 = blockIdx.x * BM;
    if (r0 >= g_poff[NE]) return;
    int e = 0;
#pragma unroll
    for (int i = 1; i < NE; i++) if (r0 >= g_poff[i]) e = i;
    const float* B = W1 + (size_t)e * HD * FF;
    int n0 = blockIdx.y * BN;
    int tid = threadIdx.x;
    if (tid < BM) stok[tid] = g_rows[r0 + tid];
    __syncthreads();

    int tx = tid & 15, ty = tid >> 4;
    int a_r = tid >> 2;         // 0..63
    int a_k = (tid & 3) * 4;    // 0,4,8,12
    int b_k = tid >> 4;         // 0..15
    int b_n = (tid & 15) * 4;
    int atok = stok[a_r];
    const float* arow = (atok >= 0) ? (x + (size_t)atok * HD) : nullptr;

    float acc[4][4];
#pragma unroll
    for (int i = 0; i < 4; i++)
#pragma unroll
        for (int j = 0; j < 4; j++) acc[i][j] = 0.f;

    for (int k0 = 0; k0 < HD; k0 += BK) {
        float4 av = make_float4(0.f, 0.f, 0.f, 0.f);
        if (arow) av = *reinterpret_cast<const float4*>(arow + k0 + a_k);
        float4 bv = *reinterpret_cast<const float4*>(B + (size_t)(k0 + b_k) * FF + n0 + b_n);
        __syncthreads();
        As[a_k + 0][a_r] = av.x;
        As[a_k + 1][a_r] = av.y;
        As[a_k + 2][a_r] = av.z;
        As[a_k + 3][a_r] = av.w;
        *reinterpret_cast<float4*>(&Bs[b_k][b_n]) = bv;
        __syncthreads();
#pragma unroll
        for (int k = 0; k < BK; k++) {
            float a[4], b[4];
#pragma unroll
            for (int i = 0; i < 4; i++) a[i] = As[k][ty * 4 + i];
#pragma unroll
            for (int j = 0; j < 4; j++) b[j] = Bs[k][tx * 4 + j];
#pragma unroll
            for (int i = 0; i < 4; i++)
#pragma unroll
                for (int j = 0; j < 4; j++) acc[i][j] += a[i] * b[j];
        }
    }

#pragma unroll
    for (int i = 0; i < 4; i++) {
        int r = r0 + ty * 4 + i;
        float4 ov;
        ov.x = gelu_f(acc[i][0]); ov.y = gelu_f(acc[i][1]);
        ov.z = gelu_f(acc[i][2]); ov.w = gelu_f(acc[i][3]);
        *reinterpret_cast<float4*>(&g_h1[(size_t)r * FF + n0 + tx * 4]) = ov;
    }
}

// ---------------- 6. GEMM2: O = H1 @ W2[e] ----------------
__global__ __launch_bounds__(256) void gemm2_kernel(const float* __restrict__ W2) {
    __shared__ float As[BK][BM + 4];
    __shared__ float Bs[BK][BN];
    int r0 = blockIdx.x * BM;
    if (r0 >= g_poff[NE]) return;
    int e = 0;
#pragma unroll
    for (int i = 1; i < NE; i++) if (r0 >= g_poff[i]) e = i;
    const float* B = W2 + (size_t)e * FF * HD;
    int n0 = blockIdx.y * BN;
    int tid = threadIdx.x;

    int tx = tid & 15, ty = tid >> 4;
    int a_r = tid >> 2;
    int a_k = (tid & 3) * 4;
    int b_k = tid >> 4;
    int b_n = (tid & 15) * 4;
    const float* arow = g_h1 + (size_t)(r0 + a_r) * FF;

    float acc[4][4];
#pragma unroll
    for (int i = 0; i < 4; i++)
#pragma unroll
        for (int j = 0; j < 4; j++) acc[i][j] = 0.f;

    for (int k0 = 0; k0 < FF; k0 += BK) {
        float4 av = *reinterpret_cast<const float4*>(arow + k0 + a_k);
        float4 bv = *reinterpret_cast<const float4*>(B + (size_t)(k0 + b_k) * HD + n0 + b_n);
        __syncthreads();
        As[a_k + 0][a_r] = av.x;
        As[a_k + 1][a_r] = av.y;
        As[a_k + 2][a_r] = av.z;
        As[a_k + 3][a_r] = av.w;
        *reinterpret_cast<float4*>(&Bs[b_k][b_n]) = bv;
        __syncthreads();
#pragma unroll
        for (int k = 0; k < BK; k++) {
            float a[4], b[4];
#pragma unroll
            for (int i = 0; i < 4; i++) a[i] = As[k][ty * 4 + i];
#pragma unroll
            for (int j = 0; j < 4; j++) b[j] = Bs[k][tx * 4 + j];
#pragma unroll
            for (int i = 0; i < 4; i++)
#pragma unroll
                for (int j = 0; j < 4; j++) acc[i][j] += a[i] * b[j];
        }
    }

#pragma unroll
    for (int i = 0; i < 4; i++) {
        int r = r0 + ty * 4 + i;
        float4 ov;
        ov.x = acc[i][0]; ov.y = acc[i][1]; ov.z = acc[i][2]; ov.w = acc[i][3];
        *reinterpret_cast<float4*>(&g_o[(size_t)r * HD + n0 + tx * 4]) = ov;
    }
}

// ---------------- 7. combine ----------------
__global__ __launch_bounds__(256) void combine_kernel(float* __restrict__ out) {
    int t = blockIdx.x;
    int r0 = g_t2r[t * 2], r1 = g_t2r[t * 2 + 1];
    float w0 = g_topw[t * 2], w1 = g_topw[t * 2 + 1];
    int c = threadIdx.x * 4;
    float4 a = *reinterpret_cast<const float4*>(g_o + (size_t)r0 * HD + c);
    float4 b = *reinterpret_cast<const float4*>(g_o + (size_t)r1 * HD + c);
    float4 o;
    o.x = w0 * a.x + w1 * b.x;
    o.y = w0 * a.y + w1 * b.y;
    o.z = w0 * a.z + w1 * b.z;
    o.w = w0 * a.w + w1 * b.w;
    *reinterpret_cast<float4*>(out + (size_t)t * HD + c) = o;
}

// ---------------- 8. aux loss (deterministic tree reduction) ----------------
__global__ __launch_bounds__(256) void aux_kernel(const float* __restrict__ logits,
                                                  float* __restrict__ aux_out) {
    __shared__ float red[256][17];
    float acc[NE], freq[NE];
#pragma unroll
    for (int e = 0; e < NE; e++) { acc[e] = 0.f; freq[e] = 0.f; }
    float z = 0.f;
    for (int t = threadIdx.x; t < NTOK; t += 256) {
        float l[NE];
#pragma unroll
        for (int e = 0; e < NE; e++) l[e] = logits[(size_t)t * NE + e];
        float m = l[0];
#pragma unroll
        for (int e = 1; e < NE; e++) m = fmaxf(m, l[e]);
        float p[NE], s = 0.f;
#pragma unroll
        for (int e = 0; e < NE; e++) { p[e] = expf(l[e] - m); s += p[e]; }
        float inv = 1.f / s;
#pragma unroll
        for (int e = 0; e < NE; e++) acc[e] += p[e] * inv;
        float lse = m + logf(s);
        z += lse * lse;
        int e0 = 0;
#pragma unroll
        for (int e = 1; e < NE; e++) if (l[e] > l[e0]) e0 = e;
        int e1 = (e0 == 0) ? 1 : 0;
#pragma unroll
        for (int e = 0; e < NE; e++) if (e != e0 && l[e] > l[e1]) e1 = e;
        freq[e0] += 1.f; freq[e1] += 1.f;
    }
    int tid = threadIdx.x;
#pragma unroll
    for (int e = 0; e < NE; e++) { red[tid][e] = acc[e]; red[tid][8 + e] = freq[e]; }
    red[tid][16] = z;
    __syncthreads();
    for (int s2 = 128; s2; s2 >>= 1) {
        if (tid < s2)
#pragma unroll
            for (int c = 0; c < 17; c++) red[tid][c] += red[tid + s2][c];
        __syncthreads();
    }
    if (tid == 0) {
        float sp = 0.f, sf = 0.f;
#pragma unroll
        for (int e = 0; e < NE; e++) { sp += red[0][e]; sf += red[0][8 + e]; }
        float sw = 0.f;
#pragma unroll
        for (int e = 0; e < NE; e++) sw += (red[0][e] / sp) * (red[0][8 + e] / sf);
        sw *= (float)NE;
        float zl = red[0][16] / (float)NTOK;
        aux_out[0] = sw + 0.1f * zl;
    }
}

// ---------------- entry ----------------
extern "C" void kernel_launch(void* const* d_in, const int* in_sizes, int n_in,
                              void* d_out, int out_size) {
    const float* x  = (const float*)d_in[0];
    const float* Wg = (const float*)d_in[1];
    const float* W1 = (const float*)d_in[2];
    const float* W2 = (const float*)d_in[3];
    float* out    = (float*)d_out;
    float* logits = out + (size_t)NTOK * HD;
    float* aux    = logits + (size_t)NTOK * NE;

    init_kernel<<<(MAXR + 255) / 256, 256>>>();
    router_kernel<<<NTOK, 128>>>(x, Wg, logits);
    offsets_kernel<<<1, 1>>>();
    scatter_kernel<<<(NTOK + 255) / 256, 256>>>();
    gemm1_kernel<<<dim3(MAXTILES, FF / BN), 256>>>(x, W1);
    gemm2_kernel<<<dim3(MAXTILES, HD / BN), 256>>>(W2);
    combine_kernel<<<NTOK, 256>>>(out);
    aux_kernel<<<1, 256>>>(logits, aux);
}

// round 3
// speedup vs baseline: 3.0274x; 3.0274x over previous
#include <cuda_runtime.h>
#include <cuda_fp16.h>
#include <math.h>
#include <stdint.h>

#define NTOK 4096
#define HD   1024
#define FF   4096
#define NE   8
#define PADM 128
#define MAXR 9216                 // 8192 + per-expert padding, multiple of 128
#define MTILES (MAXR / PADM)      // 72
#define BN   128
#define BK   32                   // K per stage
#define SAROW 40                  // smem row stride in halves (80B, conflict-free)
#define STAGE_B (3 * 128 * SAROW * 2)   // Ahi+Alo+B per stage = 30720
#define NSTAGES 3
#define SM_TOT (NSTAGES * STAGE_B)      // 92160

// ---------------- scratch ----------------
__device__ __half g_xhi[(size_t)MAXR * HD];
__device__ __half g_xlo[(size_t)MAXR * HD];
__device__ __half g_w1t[(size_t)NE * FF * HD];   // [e][n(FF)][k(HD)]
__device__ __half g_w2t[(size_t)NE * HD * FF];   // [e][n(HD)][k(FF)]
__device__ __half g_h1hi[(size_t)MAXR * FF];
__device__ __half g_h1lo[(size_t)MAXR * FF];
__device__ float  g_o[(size_t)MAXR * HD];
__device__ int    g_tope[NTOK * 2];
__device__ float  g_topw[NTOK * 2];
__device__ int    g_rows[MAXR];
__device__ int    g_t2r [NTOK * 2];
__device__ int    g_counts[NE];
__device__ int    g_cursor[NE];
__device__ int    g_poff[NE + 1];

// ---------------- PTX helpers ----------------
__device__ __forceinline__ uint32_t smem_u32(const void* p) {
    uint32_t a;
    asm("{ .reg .u64 t; cvta.to.shared.u64 t, %1; cvt.u32.u64 %0, t; }" : "=r"(a) : "l"(p));
    return a;
}
#define CPA16(dst, src) asm volatile("cp.async.cg.shared.global [%0], [%1], 16;" :: "r"(dst), "l"(src))
#define CPA_COMMIT()    asm volatile("cp.async.commit_group;" ::: "memory")
#define CPA_WAIT1()     asm volatile("cp.async.wait_group 1;" ::: "memory")
#define LDSM4(r0, r1, r2, r3, a) \
    asm volatile("ldmatrix.sync.aligned.m8n8.x4.shared.b16 {%0,%1,%2,%3}, [%4];" \
                 : "=r"(r0), "=r"(r1), "=r"(r2), "=r"(r3) : "r"(a))
#define MMA16816(d, a, b) \
    asm volatile("mma.sync.aligned.m16n8k16.row.col.f32.f16.f16.f32 " \
                 "{%0,%1,%2,%3}, {%4,%5,%6,%7}, {%8,%9}, {%0,%1,%2,%3};" \
                 : "+f"((d)[0]), "+f"((d)[1]), "+f"((d)[2]), "+f"((d)[3]) \
                 : "r"((a)[0]), "r"((a)[1]), "r"((a)[2]), "r"((a)[3]), "r"((b)[0]), "r"((b)[1]))

__device__ __forceinline__ float gelu_f(float v) {
    const float c = 0.7978845608028654f;
    float u = c * (v + 0.044715f * v * v * v);
    return 0.5f * v * (1.f + tanhf(u));
}

// ---------------- 1. init ----------------
__global__ void init_kernel() {
    int i = blockIdx.x * blockDim.x + threadIdx.x;
    if (i < MAXR) g_rows[i] = -1;
    if (i < NE) { g_counts[i] = 0; g_cursor[i] = 0; }
}

// ---------------- 2. router ----------------
__global__ __launch_bounds__(128) void router_kernel(const float* __restrict__ x,
                                                     const float* __restrict__ Wg,
                                                     float* __restrict__ logits) {
    int t = blockIdx.x;
    const float* xr = x + (size_t)t * HD;
    float acc[NE];
#pragma unroll
    for (int e = 0; e < NE; e++) acc[e] = 0.f;
    for (int j = threadIdx.x; j < HD; j += 128) {
        float xv = xr[j];
        const float4* w4 = reinterpret_cast<const float4*>(Wg + (size_t)j * NE);
        float4 wa = w4[0], wb = w4[1];
        acc[0] += xv * wa.x; acc[1] += xv * wa.y; acc[2] += xv * wa.z; acc[3] += xv * wa.w;
        acc[4] += xv * wb.x; acc[5] += xv * wb.y; acc[6] += xv * wb.z; acc[7] += xv * wb.w;
    }
    __shared__ float s[4][NE];
    int lane = threadIdx.x & 31, warp = threadIdx.x >> 5;
#pragma unroll
    for (int e = 0; e < NE; e++) {
        float v = acc[e];
#pragma unroll
        for (int o = 16; o; o >>= 1) v += __shfl_down_sync(0xffffffffu, v, o);
        if (lane == 0) s[warp][e] = v;
    }
    __syncthreads();
    if (threadIdx.x == 0) {
        float l[NE];
#pragma unroll
        for (int e = 0; e < NE; e++) {
            l[e] = s[0][e] + s[1][e] + s[2][e] + s[3][e];
            logits[(size_t)t * NE + e] = l[e];
        }
        int e0 = 0;
#pragma unroll
        for (int e = 1; e < NE; e++) if (l[e] > l[e0]) e0 = e;
        int e1 = (e0 == 0) ? 1 : 0;
#pragma unroll
        for (int e = 0; e < NE; e++) if (e != e0 && l[e] > l[e1]) e1 = e;
        float w0 = 1.f / (1.f + expf(l[e1] - l[e0]));
        float w1 = 1.f - w0;
        g_tope[t * 2] = e0; g_tope[t * 2 + 1] = e1;
        g_topw[t * 2] = w0; g_topw[t * 2 + 1] = w1;
        atomicAdd(&g_counts[e0], 1);
        atomicAdd(&g_counts[e1], 1);
    }
}

// ---------------- 3. offsets ----------------
__global__ void offsets_kernel() {
    int off = 0;
#pragma unroll
    for (int e = 0; e < NE; e++) {
        g_poff[e] = off;
        off += (g_counts[e] + PADM - 1) / PADM * PADM;
    }
    g_poff[NE] = off;
}

// ---------------- 4. scatter ----------------
__global__ void scatter_kernel() {
    int t = blockIdx.x * blockDim.x + threadIdx.x;
    if (t >= NTOK) return;
#pragma unroll
    for (int k = 0; k < 2; k++) {
        int e = g_tope[t * 2 + k];
        int slot = atomicAdd(&g_cursor[e], 1);
        int r = g_poff[e] + slot;
        g_rows[r] = t;
        g_t2r[t * 2 + k] = r;
    }
}

// ---------------- 5a. gather + split X (fp16 hi/lo) ----------------
__global__ __launch_bounds__(256) void xsplit_kernel(const float* __restrict__ x) {
    int r = blockIdx.x;
    int tok = g_rows[r];
    int c = threadIdx.x * 4;
    float4 v = make_float4(0.f, 0.f, 0.f, 0.f);
    if (tok >= 0) v = *reinterpret_cast<const float4*>(x + (size_t)tok * HD + c);
    float vv[4] = {v.x, v.y, v.z, v.w};
    __half h[4], l[4];
#pragma unroll
    for (int i = 0; i < 4; i++) {
        h[i] = __float2half_rn(vv[i]);
        l[i] = __float2half_rn(vv[i] - __half2float(h[i]));
    }
    *reinterpret_cast<uint2*>(&g_xhi[(size_t)r * HD + c]) = *reinterpret_cast<uint2*>(h);
    *reinterpret_cast<uint2*>(&g_xlo[(size_t)r * HD + c]) = *reinterpret_cast<uint2*>(l);
}

// ---------------- 5b. transpose weights to [e][n][k] fp16 ----------------
__global__ __launch_bounds__(256) void wsplit_kernel(const float* __restrict__ W,
                                                     __half* __restrict__ Wt,
                                                     int K, int N) {
    __shared__ float t[32][33];
    int e = blockIdx.z;
    int k0 = blockIdx.y * 32, n0 = blockIdx.x * 32;
    const float* src = W + (size_t)e * K * N;
    int tx = threadIdx.x, ty = threadIdx.y;     // 32 x 8
#pragma unroll
    for (int i = 0; i < 4; i++) {
        int k = ty + i * 8;
        t[k][tx] = src[(size_t)(k0 + k) * N + n0 + tx];
    }
    __syncthreads();
#pragma unroll
    for (int i = 0; i < 4; i++) {
        int n = ty + i * 8;
        Wt[((size_t)e * N + n0 + n) * K + k0 + tx] = __float2half_rn(t[tx][n]);
    }
}

// ---------------- 6. HMMA grouped GEMM ----------------
// smem per stage: Ahi [128][40] halves (10240B), Alo same, B same.
template <int KTOT, bool GELU>
__global__ __launch_bounds__(256) void mma_gemm_kernel(
    const __half* __restrict__ Ahi, const __half* __restrict__ Alo,
    const __half* __restrict__ Bmat, int Ndim,
    __half* __restrict__ OutHi, __half* __restrict__ OutLo,
    float* __restrict__ OutF)
{
    extern __shared__ char smem[];
    uint32_t sb = smem_u32(smem);
    int tid = threadIdx.x;
    int wid = tid >> 5, lane = tid & 31;

    int r0 = blockIdx.x * PADM;
    if (r0 >= g_poff[NE]) return;
    int e = 0;
#pragma unroll
    for (int i = 1; i < NE; i++) if (r0 >= g_poff[i]) e = i;
    int n0 = blockIdx.y * BN;
    const __half* Bp = Bmat + ((size_t)e * Ndim + n0) * KTOT;
    const __half* Ah = Ahi + (size_t)r0 * KTOT;
    const __half* Al = Alo + (size_t)r0 * KTOT;

    const int NS = KTOT / BK;
    int wm = wid >> 2, wn = wid & 3;    // 2 x 4 warps

    float acc[4][4][4];
#pragma unroll
    for (int mi = 0; mi < 4; mi++)
#pragma unroll
        for (int ni = 0; ni < 4; ni++)
#pragma unroll
            for (int q = 0; q < 4; q++) acc[mi][ni][q] = 0.f;

    // ---- stage loader ----
    auto load_stage = [&](int s, int bs) {
        uint32_t base = sb + bs * STAGE_B;
#pragma unroll
        for (int it = 0; it < 2; it++) {
            int idx = tid + it * 256;           // 0..511
            int row = idx >> 2, seg = idx & 3;
            uint32_t so = row * (SAROW * 2) + seg * 16;
            size_t go = (size_t)row * KTOT + s * BK + seg * 8;
            CPA16(base + so,              Ah + go);
            CPA16(base + 10240 + so,      Al + go);
            CPA16(base + 20480 + so,      Bp + go);
        }
    };

    load_stage(0, 0); CPA_COMMIT();
    load_stage(1, 1); CPA_COMMIT();

    int lr = lane & 15, lc = lane >> 4;   // ldmatrix addressing
    for (int s = 0; s < NS; s++) {
        CPA_WAIT1();
        __syncthreads();
        if (s + 2 < NS) load_stage(s + 2, (s + 2) % NSTAGES);
        CPA_COMMIT();

        uint32_t aB = sb + (s % NSTAGES) * STAGE_B;
        uint32_t alB = aB + 10240;
        uint32_t bB = aB + 20480;
#pragma unroll
        for (int ks = 0; ks < 2; ks++) {
            uint32_t ah[4][4], al[4][4], bf[4][2];
#pragma unroll
            for (int bi = 0; bi < 2; bi++) {
                uint32_t t0, t1, t2, t3;
                uint32_t addr = bB + (wn * 32 + bi * 16 + lr) * (SAROW * 2) + ks * 32 + lc * 16;
                LDSM4(t0, t1, t2, t3, addr);
                bf[bi * 2 + 0][0] = t0; bf[bi * 2 + 0][1] = t2;
                bf[bi * 2 + 1][0] = t1; bf[bi * 2 + 1][1] = t3;
            }
#pragma unroll
            for (int mi = 0; mi < 4; mi++) {
                uint32_t addr = aB + (wm * 64 + mi * 16 + lr) * (SAROW * 2) + ks * 32 + lc * 16;
                LDSM4(ah[mi][0], ah[mi][1], ah[mi][2], ah[mi][3], addr);
                uint32_t addr2 = alB + (wm * 64 + mi * 16 + lr) * (SAROW * 2) + ks * 32 + lc * 16;
                LDSM4(al[mi][0], al[mi][1], al[mi][2], al[mi][3], addr2);
            }
#pragma unroll
            for (int mi = 0; mi < 4; mi++)
#pragma unroll
                for (int ni = 0; ni < 4; ni++) {
                    MMA16816(acc[mi][ni], ah[mi], bf[ni]);
                    MMA16816(acc[mi][ni], al[mi], bf[ni]);
                }
        }
        __syncthreads();
    }

    // ---- epilogue ----
    int rbase = r0 + wm * 64 + (lane >> 2);
    int cbase = n0 + wn * 32 + (lane & 3) * 2;
#pragma unroll
    for (int mi = 0; mi < 4; mi++) {
#pragma unroll
        for (int ni = 0; ni < 4; ni++) {
#pragma unroll
            for (int half = 0; half < 2; half++) {
                int r = rbase + mi * 16 + half * 8;
                int c = cbase + ni * 8;
                float v0 = acc[mi][ni][half * 2 + 0];
                float v1 = acc[mi][ni][half * 2 + 1];
                if (GELU) {
                    v0 = gelu_f(v0); v1 = gelu_f(v1);
                    __half h0 = __float2half_rn(v0), h1 = __float2half_rn(v1);
                    __half l0 = __float2half_rn(v0 - __half2float(h0));
                    __half l1 = __float2half_rn(v1 - __half2float(h1));
                    __half2 hh = __halves2half2(h0, h1);
                    __half2 ll = __halves2half2(l0, l1);
                    *reinterpret_cast<__half2*>(&OutHi[(size_t)r * FF + c]) = hh;
                    *reinterpret_cast<__half2*>(&OutLo[(size_t)r * FF + c]) = ll;
                } else {
                    float2 o; o.x = v0; o.y = v1;
                    *reinterpret_cast<float2*>(&OutF[(size_t)r * HD + c]) = o;
                }
            }
        }
    }
}

// ---------------- 7. combine ----------------
__global__ __launch_bounds__(256) void combine_kernel(float* __restrict__ out) {
    int t = blockIdx.x;
    int r0 = g_t2r[t * 2], r1 = g_t2r[t * 2 + 1];
    float w0 = g_topw[t * 2], w1 = g_topw[t * 2 + 1];
    int c = threadIdx.x * 4;
    float4 a = *reinterpret_cast<const float4*>(g_o + (size_t)r0 * HD + c);
    float4 b = *reinterpret_cast<const float4*>(g_o + (size_t)r1 * HD + c);
    float4 o;
    o.x = w0 * a.x + w1 * b.x;
    o.y = w0 * a.y + w1 * b.y;
    o.z = w0 * a.z + w1 * b.z;
    o.w = w0 * a.w + w1 * b.w;
    *reinterpret_cast<float4*>(out + (size_t)t * HD + c) = o;
}

// ---------------- 8. aux loss ----------------
__global__ __launch_bounds__(256) void aux_kernel(const float* __restrict__ logits,
                                                  float* __restrict__ aux_out) {
    __shared__ float red[256][17];
    float acc[NE], freq[NE];
#pragma unroll
    for (int e = 0; e < NE; e++) { acc[e] = 0.f; freq[e] = 0.f; }
    float z = 0.f;
    for (int t = threadIdx.x; t < NTOK; t += 256) {
        float l[NE];
#pragma unroll
        for (int e = 0; e < NE; e++) l[e] = logits[(size_t)t * NE + e];
        float m = l[0];
#pragma unroll
        for (int e = 1; e < NE; e++) m = fmaxf(m, l[e]);
        float p[NE], s = 0.f;
#pragma unroll
        for (int e = 0; e < NE; e++) { p[e] = expf(l[e] - m); s += p[e]; }
        float inv = 1.f / s;
#pragma unroll
        for (int e = 0; e < NE; e++) acc[e] += p[e] * inv;
        float lse = m + logf(s);
        z += lse * lse;
        int e0 = 0;
#pragma unroll
        for (int e = 1; e < NE; e++) if (l[e] > l[e0]) e0 = e;
        int e1 = (e0 == 0) ? 1 : 0;
#pragma unroll
        for (int e = 0; e < NE; e++) if (e != e0 && l[e] > l[e1]) e1 = e;
        freq[e0] += 1.f; freq[e1] += 1.f;
    }
    int tid = threadIdx.x;
#pragma unroll
    for (int e = 0; e < NE; e++) { red[tid][e] = acc[e]; red[tid][8 + e] = freq[e]; }
    red[tid][16] = z;
    __syncthreads();
    for (int s2 = 128; s2; s2 >>= 1) {
        if (tid < s2)
#pragma unroll
            for (int c = 0; c < 17; c++) red[tid][c] += red[tid + s2][c];
        __syncthreads();
    }
    if (tid == 0) {
        float sp = 0.f, sf = 0.f;
#pragma unroll
        for (int e = 0; e < NE; e++) { sp += red[0][e]; sf += red[0][8 + e]; }
        float sw = 0.f;
#pragma unroll
        for (int e = 0; e < NE; e++) sw += (red[0][e] / sp) * (red[0][8 + e] / sf);
        sw *= (float)NE;
        float zl = red[0][16] / (float)NTOK;
        aux_out[0] = sw + 0.1f * zl;
    }
}

// ---------------- entry ----------------
extern "C" void kernel_launch(void* const* d_in, const int* in_sizes, int n_in,
                              void* d_out, int out_size) {
    const float* x  = (const float*)d_in[0];
    const float* Wg = (const float*)d_in[1];
    const float* W1 = (const float*)d_in[2];
    const float* W2 = (const float*)d_in[3];
    float* out    = (float*)d_out;
    float* logits = out + (size_t)NTOK * HD;
    float* aux    = logits + (size_t)NTOK * NE;

    cudaFuncSetAttribute(mma_gemm_kernel<HD, true>,
                         cudaFuncAttributeMaxDynamicSharedMemorySize, SM_TOT);
    cudaFuncSetAttribute(mma_gemm_kernel<FF, false>,
                         cudaFuncAttributeMaxDynamicSharedMemorySize, SM_TOT);

    __half *xhi, *xlo, *w1t, *w2t, *h1hi, *h1lo;
    float* o_ptr;
    cudaGetSymbolAddress((void**)&xhi,  g_xhi);
    cudaGetSymbolAddress((void**)&xlo,  g_xlo);
    cudaGetSymbolAddress((void**)&w1t,  g_w1t);
    cudaGetSymbolAddress((void**)&w2t,  g_w2t);
    cudaGetSymbolAddress((void**)&h1hi, g_h1hi);
    cudaGetSymbolAddress((void**)&h1lo, g_h1lo);
    cudaGetSymbolAddress((void**)&o_ptr, g_o);

    init_kernel<<<(MAXR + 255) / 256, 256>>>();
    router_kernel<<<NTOK, 128>>>(x, Wg, logits);
    offsets_kernel<<<1, 1>>>();
    scatter_kernel<<<(NTOK + 255) / 256, 256>>>();
    xsplit_kernel<<<MAXR, 256>>>(x);
    wsplit_kernel<<<dim3(FF / 32, HD / 32, NE), dim3(32, 8)>>>(W1, w1t, HD, FF);
    wsplit_kernel<<<dim3(HD / 32, FF / 32, NE), dim3(32, 8)>>>(W2, w2t, FF, HD);
    // GEMM1: gather(X) @ W1[e] -> gelu -> h1 (fp16 hi/lo)
    mma_gemm_kernel<HD, true><<<dim3(MTILES, FF / BN), 256, SM_TOT>>>(
        xhi, xlo, w1t, FF, h1hi, h1lo, nullptr);
    // GEMM2: h1 @ W2[e] -> g_o (fp32)
    mma_gemm_kernel<FF, false><<<dim3(MTILES, HD / BN), 256, SM_TOT>>>(
        h1hi, h1lo, w2t, HD, nullptr, nullptr, o_ptr);
    combine_kernel<<<NTOK, 256>>>(out);
    aux_kernel<<<1, 256>>>(logits, aux);
}

// round 4
// speedup vs baseline: 5.2056x; 1.7195x over previous
#include <cuda_runtime.h>
#include <cuda_fp16.h>
#include <math.h>
#include <stdint.h>

#define NTOK 4096
#define HD   1024
#define FF   4096
#define NE   8
#define PADM 128
#define MAXR 9216
#define MTILES (MAXR / PADM)      // 72
#define BN   128
#define BK   32
#define SAROW 40                        // smem row stride in halves (80B)
#define STAGE_B (2 * 128 * SAROW * 2)   // A + B per stage = 20480
#define NSTAGES 4
#define SM_TOT (NSTAGES * STAGE_B)      // 81920

// ---------------- scratch ----------------
__device__ __half g_xh[(size_t)MAXR * HD];
__device__ __half g_w1t[(size_t)NE * FF * HD];   // [e][n(FF)][k(HD)]
__device__ __half g_w2t[(size_t)NE * HD * FF];   // [e][n(HD)][k(FF)]
__device__ __half g_h1[(size_t)MAXR * FF];
__device__ float  g_o[(size_t)MAXR * HD];
__device__ int    g_tope[NTOK * 2];
__device__ float  g_topw[NTOK * 2];
__device__ int    g_rows[MAXR];
__device__ int    g_t2r [NTOK * 2];
__device__ int    g_counts[NE];
__device__ int    g_cursor[NE];
__device__ int    g_poff[NE + 1];

// ---------------- PTX helpers ----------------
__device__ __forceinline__ uint32_t smem_u32(const void* p) {
    uint32_t a;
    asm("{ .reg .u64 t; cvta.to.shared.u64 t, %1; cvt.u32.u64 %0, t; }" : "=r"(a) : "l"(p));
    return a;
}
#define CPA16(dst, src) asm volatile("cp.async.cg.shared.global [%0], [%1], 16;" :: "r"(dst), "l"(src))
#define CPA_COMMIT()    asm volatile("cp.async.commit_group;" ::: "memory")
#define CPA_WAIT2()     asm volatile("cp.async.wait_group 2;" ::: "memory")
#define LDSM4(r0, r1, r2, r3, a) \
    asm volatile("ldmatrix.sync.aligned.m8n8.x4.shared.b16 {%0,%1,%2,%3}, [%4];" \
                 : "=r"(r0), "=r"(r1), "=r"(r2), "=r"(r3) : "r"(a))
#define MMA16816(d, a, b) \
    asm volatile("mma.sync.aligned.m16n8k16.row.col.f32.f16.f16.f32 " \
                 "{%0,%1,%2,%3}, {%4,%5,%6,%7}, {%8,%9}, {%0,%1,%2,%3};" \
                 : "+f"((d)[0]), "+f"((d)[1]), "+f"((d)[2]), "+f"((d)[3]) \
                 : "r"((a)[0]), "r"((a)[1]), "r"((a)[2]), "r"((a)[3]), "r"((b)[0]), "r"((b)[1]))

__device__ __forceinline__ float gelu_f(float v) {
    const float c = 0.7978845608028654f;
    float u = c * (v + 0.044715f * v * v * v);
    return 0.5f * v * (1.f + tanhf(u));
}

// ---------------- 1. init ----------------
__global__ void init_kernel() {
    int i = blockIdx.x * blockDim.x + threadIdx.x;
    if (i < MAXR) g_rows[i] = -1;
    if (i < NE) { g_counts[i] = 0; g_cursor[i] = 0; }
}

// ---------------- 2. router ----------------
__global__ __launch_bounds__(128) void router_kernel(const float* __restrict__ x,
                                                     const float* __restrict__ Wg,
                                                     float* __restrict__ logits) {
    int t = blockIdx.x;
    const float* xr = x + (size_t)t * HD;
    float acc[NE];
#pragma unroll
    for (int e = 0; e < NE; e++) acc[e] = 0.f;
    for (int j = threadIdx.x; j < HD; j += 128) {
        float xv = xr[j];
        const float4* w4 = reinterpret_cast<const float4*>(Wg + (size_t)j * NE);
        float4 wa = w4[0], wb = w4[1];
        acc[0] += xv * wa.x; acc[1] += xv * wa.y; acc[2] += xv * wa.z; acc[3] += xv * wa.w;
        acc[4] += xv * wb.x; acc[5] += xv * wb.y; acc[6] += xv * wb.z; acc[7] += xv * wb.w;
    }
    __shared__ float s[4][NE];
    int lane = threadIdx.x & 31, warp = threadIdx.x >> 5;
#pragma unroll
    for (int e = 0; e < NE; e++) {
        float v = acc[e];
#pragma unroll
        for (int o = 16; o; o >>= 1) v += __shfl_down_sync(0xffffffffu, v, o);
        if (lane == 0) s[warp][e] = v;
    }
    __syncthreads();
    if (threadIdx.x == 0) {
        float l[NE];
#pragma unroll
        for (int e = 0; e < NE; e++) {
            l[e] = s[0][e] + s[1][e] + s[2][e] + s[3][e];
            logits[(size_t)t * NE + e] = l[e];
        }
        int e0 = 0;
#pragma unroll
        for (int e = 1; e < NE; e++) if (l[e] > l[e0]) e0 = e;
        int e1 = (e0 == 0) ? 1 : 0;
#pragma unroll
        for (int e = 0; e < NE; e++) if (e != e0 && l[e] > l[e1]) e1 = e;
        float w0 = 1.f / (1.f + expf(l[e1] - l[e0]));
        float w1 = 1.f - w0;
        g_tope[t * 2] = e0; g_tope[t * 2 + 1] = e1;
        g_topw[t * 2] = w0; g_topw[t * 2 + 1] = w1;
        atomicAdd(&g_counts[e0], 1);
        atomicAdd(&g_counts[e1], 1);
    }
}

// ---------------- 3. offsets ----------------
__global__ void offsets_kernel() {
    int off = 0;
#pragma unroll
    for (int e = 0; e < NE; e++) {
        g_poff[e] = off;
        off += (g_counts[e] + PADM - 1) / PADM * PADM;
    }
    g_poff[NE] = off;
}

// ---------------- 4. scatter ----------------
__global__ void scatter_kernel() {
    int t = blockIdx.x * blockDim.x + threadIdx.x;
    if (t >= NTOK) return;
#pragma unroll
    for (int k = 0; k < 2; k++) {
        int e = g_tope[t * 2 + k];
        int slot = atomicAdd(&g_cursor[e], 1);
        int r = g_poff[e] + slot;
        g_rows[r] = t;
        g_t2r[t * 2 + k] = r;
    }
}

// ---------------- 5a. gather X -> fp16 ----------------
__global__ __launch_bounds__(256) void xsplit_kernel(const float* __restrict__ x) {
    int r = blockIdx.x;
    int tok = g_rows[r];
    int c = threadIdx.x * 4;
    float4 v = make_float4(0.f, 0.f, 0.f, 0.f);
    if (tok >= 0) v = *reinterpret_cast<const float4*>(x + (size_t)tok * HD + c);
    __half h[4];
    h[0] = __float2half_rn(v.x); h[1] = __float2half_rn(v.y);
    h[2] = __float2half_rn(v.z); h[3] = __float2half_rn(v.w);
    *reinterpret_cast<uint2*>(&g_xh[(size_t)r * HD + c]) = *reinterpret_cast<uint2*>(h);
}

// ---------------- 5b. transpose weights to [e][n][k] fp16 ----------------
__global__ __launch_bounds__(256) void wsplit_kernel(const float* __restrict__ W,
                                                     __half* __restrict__ Wt,
                                                     int K, int N) {
    __shared__ float t[32][33];
    int e = blockIdx.z;
    int k0 = blockIdx.y * 32, n0 = blockIdx.x * 32;
    const float* src = W + (size_t)e * K * N;
    int tx = threadIdx.x, ty = threadIdx.y;
#pragma unroll
    for (int i = 0; i < 4; i++) {
        int k = ty + i * 8;
        t[k][tx] = src[(size_t)(k0 + k) * N + n0 + tx];
    }
    __syncthreads();
#pragma unroll
    for (int i = 0; i < 4; i++) {
        int n = ty + i * 8;
        Wt[((size_t)e * N + n0 + n) * K + k0 + tx] = __float2half_rn(t[tx][n]);
    }
}

// ---------------- 6. HMMA grouped GEMM (plain fp16, fp32 accum) ----------------
template <int KTOT, bool GELU>
__global__ __launch_bounds__(256, 2) void mma_gemm_kernel(
    const __half* __restrict__ Amat, const __half* __restrict__ Bmat, int Ndim,
    __half* __restrict__ OutH, float* __restrict__ OutF)
{
    extern __shared__ char smem[];
    uint32_t sb = smem_u32(smem);
    int tid = threadIdx.x;
    int wid = tid >> 5, lane = tid & 31;

    int r0 = blockIdx.x * PADM;
    if (r0 >= g_poff[NE]) return;
    int e = 0;
#pragma unroll
    for (int i = 1; i < NE; i++) if (r0 >= g_poff[i]) e = i;
    int n0 = blockIdx.y * BN;
    const __half* Bp = Bmat + ((size_t)e * Ndim + n0) * KTOT;
    const __half* Ap = Amat + (size_t)r0 * KTOT;

    const int NS = KTOT / BK;
    int wm = wid >> 2, wn = wid & 3;

    float acc[4][4][4];
#pragma unroll
    for (int mi = 0; mi < 4; mi++)
#pragma unroll
        for (int ni = 0; ni < 4; ni++)
#pragma unroll
            for (int q = 0; q < 4; q++) acc[mi][ni][q] = 0.f;

    auto load_stage = [&](int s, int bs) {
#pragma unroll
        for (int it = 0; it < 2; it++) {
            int idx = tid + it * 256;           // 0..511
            int row = idx >> 2, seg = idx & 3;
            uint32_t so = bs * STAGE_B + row * (SAROW * 2) + seg * 16;
            size_t go = (size_t)row * KTOT + s * BK + seg * 8;
            CPA16(sb + so,          Ap + go);
            CPA16(sb + 10240 + so,  Bp + go);
        }
    };

    load_stage(0, 0); CPA_COMMIT();
    load_stage(1, 1); CPA_COMMIT();
    load_stage(2, 2); CPA_COMMIT();

    int lr = lane & 15, lc = lane >> 4;
    for (int s = 0; s < NS; s++) {
        CPA_WAIT2();
        __syncthreads();
        if (s + 3 < NS) load_stage(s + 3, (s + 3) % NSTAGES);
        CPA_COMMIT();

        uint32_t aB = sb + (s % NSTAGES) * STAGE_B;
        uint32_t bB = aB + 10240;
#pragma unroll
        for (int ks = 0; ks < 2; ks++) {
            uint32_t ah[4][4], bf[4][2];
#pragma unroll
            for (int bi = 0; bi < 2; bi++) {
                uint32_t t0, t1, t2, t3;
                uint32_t addr = bB + (wn * 32 + bi * 16 + lr) * (SAROW * 2) + ks * 32 + lc * 16;
                LDSM4(t0, t1, t2, t3, addr);
                bf[bi * 2 + 0][0] = t0; bf[bi * 2 + 0][1] = t2;
                bf[bi * 2 + 1][0] = t1; bf[bi * 2 + 1][1] = t3;
            }
#pragma unroll
            for (int mi = 0; mi < 4; mi++) {
                uint32_t addr = aB + (wm * 64 + mi * 16 + lr) * (SAROW * 2) + ks * 32 + lc * 16;
                LDSM4(ah[mi][0], ah[mi][1], ah[mi][2], ah[mi][3], addr);
            }
#pragma unroll
            for (int mi = 0; mi < 4; mi++)
#pragma unroll
                for (int ni = 0; ni < 4; ni++)
                    MMA16816(acc[mi][ni], ah[mi], bf[ni]);
        }
        __syncthreads();
    }

    int rbase = r0 + wm * 64 + (lane >> 2);
    int cbase = n0 + wn * 32 + (lane & 3) * 2;
#pragma unroll
    for (int mi = 0; mi < 4; mi++) {
#pragma unroll
        for (int ni = 0; ni < 4; ni++) {
#pragma unroll
            for (int half = 0; half < 2; half++) {
                int r = rbase + mi * 16 + half * 8;
                int c = cbase + ni * 8;
                float v0 = acc[mi][ni][half * 2 + 0];
                float v1 = acc[mi][ni][half * 2 + 1];
                if (GELU) {
                    __half2 hh = __halves2half2(__float2half_rn(gelu_f(v0)),
                                                __float2half_rn(gelu_f(v1)));
                    *reinterpret_cast<__half2*>(&OutH[(size_t)r * FF + c]) = hh;
                } else {
                    float2 o; o.x = v0; o.y = v1;
                    *reinterpret_cast<float2*>(&OutF[(size_t)r * HD + c]) = o;
                }
            }
        }
    }
}

// ---------------- 7. combine ----------------
__global__ __launch_bounds__(256) void combine_kernel(float* __restrict__ out) {
    int t = blockIdx.x;
    int r0 = g_t2r[t * 2], r1 = g_t2r[t * 2 + 1];
    float w0 = g_topw[t * 2], w1 = g_topw[t * 2 + 1];
    int c = threadIdx.x * 4;
    float4 a = *reinterpret_cast<const float4*>(g_o + (size_t)r0 * HD + c);
    float4 b = *reinterpret_cast<const float4*>(g_o + (size_t)r1 * HD + c);
    float4 o;
    o.x = w0 * a.x + w1 * b.x;
    o.y = w0 * a.y + w1 * b.y;
    o.z = w0 * a.z + w1 * b.z;
    o.w = w0 * a.w + w1 * b.w;
    *reinterpret_cast<float4*>(out + (size_t)t * HD + c) = o;
}

// ---------------- 8. aux loss ----------------
__global__ __launch_bounds__(256) void aux_kernel(const float* __restrict__ logits,
                                                  float* __restrict__ aux_out) {
    __shared__ float red[256][17];
    float acc[NE], freq[NE];
#pragma unroll
    for (int e = 0; e < NE; e++) { acc[e] = 0.f; freq[e] = 0.f; }
    float z = 0.f;
    for (int t = threadIdx.x; t < NTOK; t += 256) {
        float l[NE];
#pragma unroll
        for (int e = 0; e < NE; e++) l[e] = logits[(size_t)t * NE + e];
        float m = l[0];
#pragma unroll
        for (int e = 1; e < NE; e++) m = fmaxf(m, l[e]);
        float p[NE], s = 0.f;
#pragma unroll
        for (int e = 0; e < NE; e++) { p[e] = expf(l[e] - m); s += p[e]; }
        float inv = 1.f / s;
#pragma unroll
        for (int e = 0; e < NE; e++) acc[e] += p[e] * inv;
        float lse = m + logf(s);
        z += lse * lse;
        int e0 = 0;
#pragma unroll
        for (int e = 1; e < NE; e++) if (l[e] > l[e0]) e0 = e;
        int e1 = (e0 == 0) ? 1 : 0;
#pragma unroll
        for (int e = 0; e < NE; e++) if (e != e0 && l[e] > l[e1]) e1 = e;
        freq[e0] += 1.f; freq[e1] += 1.f;
    }
    int tid = threadIdx.x;
#pragma unroll
    for (int e = 0; e < NE; e++) { red[tid][e] = acc[e]; red[tid][8 + e] = freq[e]; }
    red[tid][16] = z;
    __syncthreads();
    for (int s2 = 128; s2; s2 >>= 1) {
        if (tid < s2)
#pragma unroll
            for (int c = 0; c < 17; c++) red[tid][c] += red[tid + s2][c];
        __syncthreads();
    }
    if (tid == 0) {
        float sp = 0.f, sf = 0.f;
#pragma unroll
        for (int e = 0; e < NE; e++) { sp += red[0][e]; sf += red[0][8 + e]; }
        float sw = 0.f;
#pragma unroll
        for (int e = 0; e < NE; e++) sw += (red[0][e] / sp) * (red[0][8 + e] / sf);
        sw *= (float)NE;
        float zl = red[0][16] / (float)NTOK;
        aux_out[0] = sw + 0.1f * zl;
    }
}

// ---------------- entry ----------------
extern "C" void kernel_launch(void* const* d_in, const int* in_sizes, int n_in,
                              void* d_out, int out_size) {
    const float* x  = (const float*)d_in[0];
    const float* Wg = (const float*)d_in[1];
    const float* W1 = (const float*)d_in[2];
    const float* W2 = (const float*)d_in[3];
    float* out    = (float*)d_out;
    float* logits = out + (size_t)NTOK * HD;
    float* aux    = logits + (size_t)NTOK * NE;

    cudaFuncSetAttribute(mma_gemm_kernel<HD, true>,
                         cudaFuncAttributeMaxDynamicSharedMemorySize, SM_TOT);
    cudaFuncSetAttribute(mma_gemm_kernel<FF, false>,
                         cudaFuncAttributeMaxDynamicSharedMemorySize, SM_TOT);

    __half *xh, *w1t, *w2t, *h1;
    float* o_ptr;
    cudaGetSymbolAddress((void**)&xh,  g_xh);
    cudaGetSymbolAddress((void**)&w1t, g_w1t);
    cudaGetSymbolAddress((void**)&w2t, g_w2t);
    cudaGetSymbolAddress((void**)&h1,  g_h1);
    cudaGetSymbolAddress((void**)&o_ptr, g_o);

    init_kernel<<<(MAXR + 255) / 256, 256>>>();
    router_kernel<<<NTOK, 128>>>(x, Wg, logits);
    offsets_kernel<<<1, 1>>>();
    scatter_kernel<<<(NTOK + 255) / 256, 256>>>();
    xsplit_kernel<<<MAXR, 256>>>(x);
    wsplit_kernel<<<dim3(FF / 32, HD / 32, NE), dim3(32, 8)>>>(W1, w1t, HD, FF);
    wsplit_kernel<<<dim3(HD / 32, FF / 32, NE), dim3(32, 8)>>>(W2, w2t, FF, HD);
    mma_gemm_kernel<HD, true><<<dim3(MTILES, FF / BN), 256, SM_TOT>>>(xh, w1t, FF, h1, nullptr);
    mma_gemm_kernel<FF, false><<<dim3(MTILES, HD / BN), 256, SM_TOT>>>(h1, w2t, HD, nullptr, o_ptr);
    combine_kernel<<<NTOK, 256>>>(out);
    aux_kernel<<<1, 256>>>(logits, aux);
}